// round 1
// baseline (speedup 1.0000x reference)
#include <cuda_runtime.h>
#include <cstdint>
#include <cstddef>

// Problem shape (fixed by the dataset)
#define BT   8192      // B*T tokens
#define IN_F 4096
#define OUT_F 4096
#define NEXP 8
#define RLOR 16
#define ERC  128       // E * R  (LoRA "wide" dim)

// GEMM tiling
#define BM 128
#define BN 128
#define BKT 32
#define PADA 36        // smemA row stride in floats (bank-conflict-free for frag loads)
#define PADB 132       // smemB row stride in floats
#define SA_SZ (BM * PADA)          // 4608 u32
#define SB_SZ (BKT * PADB)         // 4224 u32
#define SMEM_BYTES ((2 * SA_SZ + 2 * SB_SZ) * 4)   // 70656 B

// Scratch (no device allocation allowed -> __device__ globals)
__device__ float g_si[(size_t)BT * ERC];        // 4 MB: scaled LoRA intermediate
__device__ float g_Ball[(size_t)OUT_F * ERC];   // 2 MB: B_w repacked [O][E*R]

__device__ __forceinline__ uint32_t f2tf32(float x) {
    uint32_t r;
    asm("cvt.rna.tf32.f32 %0, %1;" : "=r"(r) : "f"(x));
    return r;
}

__device__ __forceinline__ void mma_tf32(float c[4],
                                         uint32_t a0, uint32_t a1, uint32_t a2, uint32_t a3,
                                         uint32_t b0, uint32_t b1) {
    asm volatile(
        "mma.sync.aligned.m16n8k8.row.col.f32.tf32.tf32.f32 "
        "{%0,%1,%2,%3}, {%4,%5,%6,%7}, {%8,%9}, {%0,%1,%2,%3};"
        : "+f"(c[0]), "+f"(c[1]), "+f"(c[2]), "+f"(c[3])
        : "r"(a0), "r"(a1), "r"(a2), "r"(a3), "r"(b0), "r"(b1));
}

// ---------------------------------------------------------------------------
// Dual-phase TF32 GEMM:  C[m][n] = sum_k A0[m][k]*B0[n][k]  (K0)
//                               + sum_k A1[m][k]*B1[n][k]  (K1, optional)
//                               + bias[n] (optional)
// A row-major [M][lda], B row-major [N][ldb] (i.e. computes A @ B^T).
// ---------------------------------------------------------------------------
__global__ __launch_bounds__(256, 1)
void gemm_tf32_kernel(const float* __restrict__ A0, int lda0,
                      const float* __restrict__ B0, int ldb0, int K0,
                      const float* __restrict__ A1, int lda1,
                      const float* __restrict__ B1, int ldb1, int K1,
                      float* __restrict__ C, int ldc,
                      const float* __restrict__ bias)
{
    extern __shared__ uint32_t smem_u[];
    uint32_t* sA = smem_u;                 // [2][SA_SZ]  layout: [row][k] stride PADA
    uint32_t* sB = smem_u + 2 * SA_SZ;     // [2][SB_SZ]  layout: [k][n]  stride PADB

    const int tid  = threadIdx.x;
    const int bm   = blockIdx.y * BM;
    const int bn   = blockIdx.x * BN;
    const int warp = tid >> 5;
    const int lane = tid & 31;
    const int wm   = (warp >> 2) * 64;   // 2 warps along M
    const int wn   = (warp & 3) * 32;    // 4 warps along N
    const int g    = lane >> 2;          // 0..7
    const int t4   = lane & 3;           // 0..3

    float acc[4][4][4];
    #pragma unroll
    for (int i = 0; i < 4; i++)
        #pragma unroll
        for (int j = 0; j < 4; j++)
            #pragma unroll
            for (int v = 0; v < 4; v++) acc[i][j][v] = 0.f;

    // Loader indexing
    const int a_row = tid >> 3;            // 0..31 (x4 slabs of 32 rows)
    const int a_col = (tid & 7) * 4;       // 0..28
    const int b_n   = tid & 127;           // 0..127
    const int b_kb  = tid >> 7;            // 0 or 1

    float4 ra[4], rb[4];

    auto ldg = [&](const float* A, int lda, const float* B, int ldb, int k0) {
        #pragma unroll
        for (int i = 0; i < 4; i++) {
            int row = a_row + i * 32;
            ra[i] = *(const float4*)(A + (size_t)(bm + row) * lda + k0 + a_col);
        }
        #pragma unroll
        for (int j = 0; j < 4; j++) {
            int kf4 = b_kb + 2 * j;        // 0..7
            rb[j] = *(const float4*)(B + (size_t)(bn + b_n) * ldb + k0 + kf4 * 4);
        }
    };

    auto sts = [&](int buf) {
        uint32_t* a = sA + buf * SA_SZ;
        uint32_t* b = sB + buf * SB_SZ;
        #pragma unroll
        for (int i = 0; i < 4; i++) {
            int row = a_row + i * 32;
            uint4 w;
            w.x = f2tf32(ra[i].x); w.y = f2tf32(ra[i].y);
            w.z = f2tf32(ra[i].z); w.w = f2tf32(ra[i].w);
            *(uint4*)(a + row * PADA + a_col) = w;
        }
        #pragma unroll
        for (int j = 0; j < 4; j++) {
            int kf4 = b_kb + 2 * j;
            b[(kf4 * 4 + 0) * PADB + b_n] = f2tf32(rb[j].x);
            b[(kf4 * 4 + 1) * PADB + b_n] = f2tf32(rb[j].y);
            b[(kf4 * 4 + 2) * PADB + b_n] = f2tf32(rb[j].z);
            b[(kf4 * 4 + 3) * PADB + b_n] = f2tf32(rb[j].w);
        }
    };

    auto compute = [&](int buf) {
        const uint32_t* a = sA + buf * SA_SZ;
        const uint32_t* b = sB + buf * SB_SZ;
        #pragma unroll
        for (int ks = 0; ks < 4; ks++) {
            const int k = ks * 8;
            uint32_t af[4][4], bf[4][2];
            #pragma unroll
            for (int mt = 0; mt < 4; mt++) {
                int r0 = wm + mt * 16;
                af[mt][0] = a[(r0 + g)     * PADA + k + t4];
                af[mt][1] = a[(r0 + g + 8) * PADA + k + t4];
                af[mt][2] = a[(r0 + g)     * PADA + k + t4 + 4];
                af[mt][3] = a[(r0 + g + 8) * PADA + k + t4 + 4];
            }
            #pragma unroll
            for (int nt = 0; nt < 4; nt++) {
                int nb = wn + nt * 8 + g;
                bf[nt][0] = b[(k + t4)     * PADB + nb];
                bf[nt][1] = b[(k + t4 + 4) * PADB + nb];
            }
            #pragma unroll
            for (int mt = 0; mt < 4; mt++)
                #pragma unroll
                for (int nt = 0; nt < 4; nt++)
                    mma_tf32(acc[mt][nt], af[mt][0], af[mt][1], af[mt][2], af[mt][3],
                             bf[nt][0], bf[nt][1]);
        }
    };

    const int T0 = K0 / BKT;
    const int T1 = K1 / BKT;
    const int T  = T0 + T1;

    auto ldg_t = [&](int t) {
        if (t < T0) ldg(A0, lda0, B0, ldb0, t * BKT);
        else        ldg(A1, lda1, B1, ldb1, (t - T0) * BKT);
    };

    ldg_t(0);
    sts(0);
    __syncthreads();

    for (int t = 0; t < T; t++) {
        const int cur = t & 1;
        if (t + 1 < T) ldg_t(t + 1);
        compute(cur);
        if (t + 1 < T) sts(cur ^ 1);
        __syncthreads();
    }

    // Epilogue
    #pragma unroll
    for (int mt = 0; mt < 4; mt++) {
        #pragma unroll
        for (int nt = 0; nt < 4; nt++) {
            const int row0 = bm + wm + mt * 16 + g;
            const int col0 = bn + wn + nt * 8 + t4 * 2;
            float bv0 = 0.f, bv1 = 0.f;
            if (bias) { bv0 = bias[col0]; bv1 = bias[col0 + 1]; }
            float2 o0 = make_float2(acc[mt][nt][0] + bv0, acc[mt][nt][1] + bv1);
            float2 o1 = make_float2(acc[mt][nt][2] + bv0, acc[mt][nt][3] + bv1);
            *(float2*)(C + (size_t)row0 * ldc + col0)       = o0;
            *(float2*)(C + (size_t)(row0 + 8) * ldc + col0) = o1;
        }
    }
}

// ---------------------------------------------------------------------------
// Repack B_w [E][O][R] -> g_Ball [O][E*R]
// ---------------------------------------------------------------------------
__global__ void prep_ball_kernel(const float* __restrict__ Bw)
{
    int idx = blockIdx.x * blockDim.x + threadIdx.x;   // 0 .. O*ERC-1
    int o = idx >> 7;
    int c = idx & 127;
    g_Ball[idx] = Bw[(size_t)(c >> 4) * OUT_F * RLOR + (size_t)o * RLOR + (c & 15)];
}

// ---------------------------------------------------------------------------
// Router (exact fp32) + top-2 softmax + in-place scaling of g_si rows.
// One warp per token.
// ---------------------------------------------------------------------------
__global__ void router_mask_kernel(const float* __restrict__ x,
                                   const float* __restrict__ Wr,   // [E][IN]
                                   float* __restrict__ si)         // [BT][ERC]
{
    const int tok  = (blockIdx.x * blockDim.x + threadIdx.x) >> 5;
    const int lane = threadIdx.x & 31;
    if (tok >= BT) return;

    const float* xr = x + (size_t)tok * IN_F;
    float acc[NEXP];
    #pragma unroll
    for (int e = 0; e < NEXP; e++) acc[e] = 0.f;

    for (int k = lane * 4; k < IN_F; k += 128) {
        float4 xv = *(const float4*)(xr + k);
        #pragma unroll
        for (int e = 0; e < NEXP; e++) {
            float4 wv = *(const float4*)(Wr + (size_t)e * IN_F + k);
            acc[e] += xv.x * wv.x + xv.y * wv.y + xv.z * wv.z + xv.w * wv.w;
        }
    }
    #pragma unroll
    for (int e = 0; e < NEXP; e++)
        #pragma unroll
        for (int off = 16; off > 0; off >>= 1)
            acc[e] += __shfl_xor_sync(0xFFFFFFFFu, acc[e], off);

    // top-2 (ties -> lower index, matching jax.lax.top_k)
    int i0 = 0; float v0 = acc[0];
    #pragma unroll
    for (int e = 1; e < NEXP; e++) if (acc[e] > v0) { v0 = acc[e]; i0 = e; }
    int i1 = -1; float v1 = -3.4e38f;
    #pragma unroll
    for (int e = 0; e < NEXP; e++) if (e != i0 && acc[e] > v1) { v1 = acc[e]; i1 = e; }

    const float ex = expf(v1 - v0);          // v0 >= v1
    const float w0 = 1.f / (1.f + ex);
    const float w1 = ex / (1.f + ex);
    // SCALING = LORA_ALPHA / R = 1.0 -> folded

    float* s = si + (size_t)tok * ERC;
    #pragma unroll
    for (int j = 0; j < 4; j++) {
        int c = lane + j * 32;
        int e = c >> 4;
        float f = (e == i0) ? w0 : (e == i1) ? w1 : 0.f;
        s[c] *= f;
    }
}

// ---------------------------------------------------------------------------
extern "C" void kernel_launch(void* const* d_in, const int* in_sizes, int n_in,
                              void* d_out, int out_size)
{
    const float* x  = (const float*)d_in[0];   // [B,T,IN]
    const float* Wb = (const float*)d_in[1];   // [OUT,IN]
    const float* bb = (const float*)d_in[2];   // [OUT]
    const float* Wr = (const float*)d_in[3];   // [E,IN]
    const float* Aw = (const float*)d_in[4];   // [E,R,IN] == A_all [ERC][IN]
    const float* Bw = (const float*)d_in[5];   // [E,OUT,R]
    float* out = (float*)d_out;

    float *si, *ball;
    cudaGetSymbolAddress((void**)&si,   g_si);
    cudaGetSymbolAddress((void**)&ball, g_Ball);

    cudaFuncSetAttribute(gemm_tf32_kernel,
                         cudaFuncAttributeMaxDynamicSharedMemorySize, SMEM_BYTES);

    // 1) repack B_w
    prep_ball_kernel<<<(OUT_F * ERC) / 256, 256>>>(Bw);

    // 2) si = x @ A_all^T   (M=8192, N=128, K=4096)
    dim3 g1(ERC / BN, BT / BM);
    gemm_tf32_kernel<<<g1, 256, SMEM_BYTES>>>(
        x, IN_F, Aw, IN_F, IN_F,
        nullptr, 0, nullptr, 0, 0,
        si, ERC, nullptr);

    // 3) router + top-2 softmax + scale si in place
    router_mask_kernel<<<BT / 8, 256>>>(x, Wr, si);

    // 4) out = x @ W_base^T + si @ B_all^T + b
    dim3 g2(OUT_F / BN, BT / BM);
    gemm_tf32_kernel<<<g2, 256, SMEM_BYTES>>>(
        x, IN_F, Wb, IN_F, IN_F,
        si, ERC, ball, ERC, ERC,
        out, OUT_F, bb);
}

// round 2
// speedup vs baseline: 1.0008x; 1.0008x over previous
#include <cuda_runtime.h>
#include <cstdint>
#include <cstddef>

// Problem shape (fixed by the dataset)
#define BT   8192      // B*T tokens
#define IN_F 4096
#define OUT_F 4096
#define NEXP 8
#define RLOR 16
#define ERC  128       // E * R  (LoRA "wide" dim)

// GEMM tiling
#define BM 128
#define BN 128
#define BKT 32
#define PADA 36        // smemA row stride in floats (bank-conflict-free for frag loads)
#define PADB 132       // smemB row stride in floats
#define SA_SZ (BM * PADA)          // 4608 u32
#define SB_SZ (BKT * PADB)         // 4224 u32
#define SMEM_BYTES ((2 * SA_SZ + 2 * SB_SZ) * 4)   // 70656 B

// Scratch (no device allocation allowed -> __device__ globals)
__device__ float g_si[(size_t)BT * ERC];        // 4 MB: scaled LoRA intermediate
__device__ float g_Ball[(size_t)OUT_F * ERC];   // 2 MB: B_w repacked [O][E*R]

__device__ __forceinline__ uint32_t f2tf32(float x) {
    uint32_t r;
    asm("cvt.rna.tf32.f32 %0, %1;" : "=r"(r) : "f"(x));
    return r;
}

__device__ __forceinline__ void mma_tf32(float c[4],
                                         uint32_t a0, uint32_t a1, uint32_t a2, uint32_t a3,
                                         uint32_t b0, uint32_t b1) {
    asm volatile(
        "mma.sync.aligned.m16n8k8.row.col.f32.tf32.tf32.f32 "
        "{%0,%1,%2,%3}, {%4,%5,%6,%7}, {%8,%9}, {%0,%1,%2,%3};"
        : "+f"(c[0]), "+f"(c[1]), "+f"(c[2]), "+f"(c[3])
        : "r"(a0), "r"(a1), "r"(a2), "r"(a3), "r"(b0), "r"(b1));
}

// ---------------------------------------------------------------------------
// Dual-phase TF32 GEMM:  C[m][n] = sum_k A0[m][k]*B0[n][k]  (K0)
//                               + sum_k A1[m][k]*B1[n][k]  (K1, optional)
//                               + bias[n] (optional)
// A row-major [M][lda], B row-major [N][ldb] (i.e. computes A @ B^T).
// ---------------------------------------------------------------------------
__global__ __launch_bounds__(256, 1)
void gemm_tf32_kernel(const float* __restrict__ A0, int lda0,
                      const float* __restrict__ B0, int ldb0, int K0,
                      const float* __restrict__ A1, int lda1,
                      const float* __restrict__ B1, int ldb1, int K1,
                      float* __restrict__ C, int ldc,
                      const float* __restrict__ bias)
{
    extern __shared__ uint32_t smem_u[];
    uint32_t* sA = smem_u;                 // [2][SA_SZ]  layout: [row][k] stride PADA
    uint32_t* sB = smem_u + 2 * SA_SZ;     // [2][SB_SZ]  layout: [k][n]  stride PADB

    const int tid  = threadIdx.x;
    const int bm   = blockIdx.y * BM;
    const int bn   = blockIdx.x * BN;
    const int warp = tid >> 5;
    const int lane = tid & 31;
    const int wm   = (warp >> 2) * 64;   // 2 warps along M
    const int wn   = (warp & 3) * 32;    // 4 warps along N
    const int g    = lane >> 2;          // 0..7
    const int t4   = lane & 3;           // 0..3

    float acc[4][4][4];
    #pragma unroll
    for (int i = 0; i < 4; i++)
        #pragma unroll
        for (int j = 0; j < 4; j++)
            #pragma unroll
            for (int v = 0; v < 4; v++) acc[i][j][v] = 0.f;

    // Loader indexing
    const int a_row = tid >> 3;            // 0..31 (x4 slabs of 32 rows)
    const int a_col = (tid & 7) * 4;       // 0..28
    const int b_n   = tid & 127;           // 0..127
    const int b_kb  = tid >> 7;            // 0 or 1

    float4 ra[4], rb[4];

    auto ldg = [&](const float* A, int lda, const float* B, int ldb, int k0) {
        #pragma unroll
        for (int i = 0; i < 4; i++) {
            int row = a_row + i * 32;
            ra[i] = *(const float4*)(A + (size_t)(bm + row) * lda + k0 + a_col);
        }
        #pragma unroll
        for (int j = 0; j < 4; j++) {
            int kf4 = b_kb + 2 * j;        // 0..7
            rb[j] = *(const float4*)(B + (size_t)(bn + b_n) * ldb + k0 + kf4 * 4);
        }
    };

    auto sts = [&](int buf) {
        uint32_t* a = sA + buf * SA_SZ;
        uint32_t* b = sB + buf * SB_SZ;
        #pragma unroll
        for (int i = 0; i < 4; i++) {
            int row = a_row + i * 32;
            uint4 w;
            w.x = f2tf32(ra[i].x); w.y = f2tf32(ra[i].y);
            w.z = f2tf32(ra[i].z); w.w = f2tf32(ra[i].w);
            *(uint4*)(a + row * PADA + a_col) = w;
        }
        #pragma unroll
        for (int j = 0; j < 4; j++) {
            int kf4 = b_kb + 2 * j;
            b[(kf4 * 4 + 0) * PADB + b_n] = f2tf32(rb[j].x);
            b[(kf4 * 4 + 1) * PADB + b_n] = f2tf32(rb[j].y);
            b[(kf4 * 4 + 2) * PADB + b_n] = f2tf32(rb[j].z);
            b[(kf4 * 4 + 3) * PADB + b_n] = f2tf32(rb[j].w);
        }
    };

    auto compute = [&](int buf) {
        const uint32_t* a = sA + buf * SA_SZ;
        const uint32_t* b = sB + buf * SB_SZ;
        #pragma unroll
        for (int ks = 0; ks < 4; ks++) {
            const int k = ks * 8;
            uint32_t af[4][4], bf[4][2];
            #pragma unroll
            for (int mt = 0; mt < 4; mt++) {
                int r0 = wm + mt * 16;
                af[mt][0] = a[(r0 + g)     * PADA + k + t4];
                af[mt][1] = a[(r0 + g + 8) * PADA + k + t4];
                af[mt][2] = a[(r0 + g)     * PADA + k + t4 + 4];
                af[mt][3] = a[(r0 + g + 8) * PADA + k + t4 + 4];
            }
            #pragma unroll
            for (int nt = 0; nt < 4; nt++) {
                int nb = wn + nt * 8 + g;
                bf[nt][0] = b[(k + t4)     * PADB + nb];
                bf[nt][1] = b[(k + t4 + 4) * PADB + nb];
            }
            #pragma unroll
            for (int mt = 0; mt < 4; mt++)
                #pragma unroll
                for (int nt = 0; nt < 4; nt++)
                    mma_tf32(acc[mt][nt], af[mt][0], af[mt][1], af[mt][2], af[mt][3],
                             bf[nt][0], bf[nt][1]);
        }
    };

    const int T0 = K0 / BKT;
    const int T1 = K1 / BKT;
    const int T  = T0 + T1;

    auto ldg_t = [&](int t) {
        if (t < T0) ldg(A0, lda0, B0, ldb0, t * BKT);
        else        ldg(A1, lda1, B1, ldb1, (t - T0) * BKT);
    };

    ldg_t(0);
    sts(0);
    __syncthreads();

    for (int t = 0; t < T; t++) {
        const int cur = t & 1;
        if (t + 1 < T) ldg_t(t + 1);
        compute(cur);
        if (t + 1 < T) sts(cur ^ 1);
        __syncthreads();
    }

    // Epilogue
    #pragma unroll
    for (int mt = 0; mt < 4; mt++) {
        #pragma unroll
        for (int nt = 0; nt < 4; nt++) {
            const int row0 = bm + wm + mt * 16 + g;
            const int col0 = bn + wn + nt * 8 + t4 * 2;
            float bv0 = 0.f, bv1 = 0.f;
            if (bias) { bv0 = bias[col0]; bv1 = bias[col0 + 1]; }
            float2 o0 = make_float2(acc[mt][nt][0] + bv0, acc[mt][nt][1] + bv1);
            float2 o1 = make_float2(acc[mt][nt][2] + bv0, acc[mt][nt][3] + bv1);
            *(float2*)(C + (size_t)row0 * ldc + col0)       = o0;
            *(float2*)(C + (size_t)(row0 + 8) * ldc + col0) = o1;
        }
    }
}

// ---------------------------------------------------------------------------
// Repack B_w [E][O][R] -> g_Ball [O][E*R]
// ---------------------------------------------------------------------------
__global__ void prep_ball_kernel(const float* __restrict__ Bw)
{
    int idx = blockIdx.x * blockDim.x + threadIdx.x;   // 0 .. O*ERC-1
    int o = idx >> 7;
    int c = idx & 127;
    g_Ball[idx] = Bw[(size_t)(c >> 4) * OUT_F * RLOR + (size_t)o * RLOR + (c & 15)];
}

// ---------------------------------------------------------------------------
// Router (exact fp32) + top-2 softmax + in-place scaling of g_si rows.
// One warp per token.
// ---------------------------------------------------------------------------
__global__ void router_mask_kernel(const float* __restrict__ x,
                                   const float* __restrict__ Wr,   // [E][IN]
                                   float* __restrict__ si)         // [BT][ERC]
{
    const int tok  = (blockIdx.x * blockDim.x + threadIdx.x) >> 5;
    const int lane = threadIdx.x & 31;
    if (tok >= BT) return;

    const float* xr = x + (size_t)tok * IN_F;
    float acc[NEXP];
    #pragma unroll
    for (int e = 0; e < NEXP; e++) acc[e] = 0.f;

    for (int k = lane * 4; k < IN_F; k += 128) {
        float4 xv = *(const float4*)(xr + k);
        #pragma unroll
        for (int e = 0; e < NEXP; e++) {
            float4 wv = *(const float4*)(Wr + (size_t)e * IN_F + k);
            acc[e] += xv.x * wv.x + xv.y * wv.y + xv.z * wv.z + xv.w * wv.w;
        }
    }
    #pragma unroll
    for (int e = 0; e < NEXP; e++)
        #pragma unroll
        for (int off = 16; off > 0; off >>= 1)
            acc[e] += __shfl_xor_sync(0xFFFFFFFFu, acc[e], off);

    // top-2 (ties -> lower index, matching jax.lax.top_k)
    int i0 = 0; float v0 = acc[0];
    #pragma unroll
    for (int e = 1; e < NEXP; e++) if (acc[e] > v0) { v0 = acc[e]; i0 = e; }
    int i1 = -1; float v1 = -3.4e38f;
    #pragma unroll
    for (int e = 0; e < NEXP; e++) if (e != i0 && acc[e] > v1) { v1 = acc[e]; i1 = e; }

    const float ex = expf(v1 - v0);          // v0 >= v1
    const float w0 = 1.f / (1.f + ex);
    const float w1 = ex / (1.f + ex);
    // SCALING = LORA_ALPHA / R = 1.0 -> folded

    float* s = si + (size_t)tok * ERC;
    #pragma unroll
    for (int j = 0; j < 4; j++) {
        int c = lane + j * 32;
        int e = c >> 4;
        float f = (e == i0) ? w0 : (e == i1) ? w1 : 0.f;
        s[c] *= f;
    }
}

// ---------------------------------------------------------------------------
extern "C" void kernel_launch(void* const* d_in, const int* in_sizes, int n_in,
                              void* d_out, int out_size)
{
    const float* x  = (const float*)d_in[0];   // [B,T,IN]
    const float* Wb = (const float*)d_in[1];   // [OUT,IN]
    const float* bb = (const float*)d_in[2];   // [OUT]
    const float* Wr = (const float*)d_in[3];   // [E,IN]
    const float* Aw = (const float*)d_in[4];   // [E,R,IN] == A_all [ERC][IN]
    const float* Bw = (const float*)d_in[5];   // [E,OUT,R]
    float* out = (float*)d_out;

    float *si, *ball;
    cudaGetSymbolAddress((void**)&si,   g_si);
    cudaGetSymbolAddress((void**)&ball, g_Ball);

    cudaFuncSetAttribute(gemm_tf32_kernel,
                         cudaFuncAttributeMaxDynamicSharedMemorySize, SMEM_BYTES);

    // 1) repack B_w
    prep_ball_kernel<<<(OUT_F * ERC) / 256, 256>>>(Bw);

    // 2) si = x @ A_all^T   (M=8192, N=128, K=4096)
    dim3 g1(ERC / BN, BT / BM);
    gemm_tf32_kernel<<<g1, 256, SMEM_BYTES>>>(
        x, IN_F, Aw, IN_F, IN_F,
        nullptr, 0, nullptr, 0, 0,
        si, ERC, nullptr);

    // 3) router + top-2 softmax + scale si in place
    router_mask_kernel<<<BT / 8, 256>>>(x, Wr, si);

    // 4) out = x @ W_base^T + si @ B_all^T + b
    dim3 g2(OUT_F / BN, BT / BM);
    gemm_tf32_kernel<<<g2, 256, SMEM_BYTES>>>(
        x, IN_F, Wb, IN_F, IN_F,
        si, ERC, ball, ERC, ERC,
        out, OUT_F, bb);
}

// round 4
// speedup vs baseline: 1.6493x; 1.6480x over previous
#include <cuda_runtime.h>
#include <cstdint>
#include <cstddef>

// Problem shape (fixed by the dataset)
#define BT   8192      // B*T tokens
#define IN_F 4096
#define OUT_F 4096
#define NEXP 8
#define RLOR 16
#define ERC  128       // E * R  (LoRA "wide" dim)
#define KSPLIT 4       // split-K factor for GEMM1

// GEMM tiling
#define BM 128
#define BN 128
#define BKT 32
#define PADA 36        // smemA row stride in floats (bank-conflict-free)
#define PADB 36        // smemB row stride in floats (n-major, same pattern as A)
#define SA_SZ (BM * PADA)          // 4608 u32
#define SB_SZ (BN * PADB)          // 4608 u32
#define SMEM_BYTES ((2 * SA_SZ + 2 * SB_SZ) * 4)   // 73728 B

// Scratch (no device allocation allowed -> __device__ globals)
__device__ float g_si[(size_t)KSPLIT * BT * ERC];   // 16 MB: split-K partials (part 0 = final)
__device__ float g_Ball[(size_t)OUT_F * ERC];       // 2 MB: B_w repacked [O][E*R]

__device__ __forceinline__ uint32_t f2tf32(float x) {
    uint32_t r;
    asm("cvt.rna.tf32.f32 %0, %1;" : "=r"(r) : "f"(x));
    return r;
}

__device__ __forceinline__ void mma_tf32(float c[4],
                                         uint32_t a0, uint32_t a1, uint32_t a2, uint32_t a3,
                                         uint32_t b0, uint32_t b1) {
    asm volatile(
        "mma.sync.aligned.m16n8k8.row.col.f32.tf32.tf32.f32 "
        "{%0,%1,%2,%3}, {%4,%5,%6,%7}, {%8,%9}, {%0,%1,%2,%3};"
        : "+f"(c[0]), "+f"(c[1]), "+f"(c[2]), "+f"(c[3])
        : "r"(a0), "r"(a1), "r"(a2), "r"(a3), "r"(b0), "r"(b1));
}

// ---------------------------------------------------------------------------
// Dual-phase TF32 GEMM:  C[m][n] = sum_k A0[m][k]*B0[n][k]  (K0)
//                               + sum_k A1[m][k]*B1[n][k]  (K1, optional)
//                               + bias[n] (optional)
// A row-major [M][lda], B row-major [N][ldb] (computes A @ B^T).
// blockIdx.z = split-K slice: offsets A0/B0 by z*K0 elements along K and C by
// z*cpart elements (cpart = partial-buffer stride). Use gridDim.z==1 for no split.
// ---------------------------------------------------------------------------
__global__ __launch_bounds__(256, 1)
void gemm_tf32_kernel(const float* __restrict__ A0, int lda0,
                      const float* __restrict__ B0, int ldb0, int K0,
                      const float* __restrict__ A1, int lda1,
                      const float* __restrict__ B1, int ldb1, int K1,
                      float* __restrict__ C, int ldc,
                      const float* __restrict__ bias,
                      size_t cpart)
{
    extern __shared__ uint32_t smem_u[];
    uint32_t* sA = smem_u;                 // [2][SA_SZ]  layout: [row][k] stride PADA
    uint32_t* sB = smem_u + 2 * SA_SZ;     // [2][SB_SZ]  layout: [n][k]  stride PADB

    const int z = blockIdx.z;
    A0 += (size_t)z * K0;
    B0 += (size_t)z * K0;
    C  += (size_t)z * cpart;

    const int tid  = threadIdx.x;
    const int bm   = blockIdx.y * BM;
    const int bn   = blockIdx.x * BN;
    const int warp = tid >> 5;
    const int lane = tid & 31;
    const int wm   = (warp >> 2) * 64;   // 2 warps along M
    const int wn   = (warp & 3) * 32;    // 4 warps along N
    const int g    = lane >> 2;          // 0..7
    const int t4   = lane & 3;           // 0..3

    float acc[4][4][4];
    #pragma unroll
    for (int i = 0; i < 4; i++)
        #pragma unroll
        for (int j = 0; j < 4; j++)
            #pragma unroll
            for (int v = 0; v < 4; v++) acc[i][j][v] = 0.f;

    // Loader indexing (identical pattern for A and B: 4 slabs of 32 rows)
    const int l_row = tid >> 3;            // 0..31
    const int l_col = (tid & 7) * 4;       // 0..28

    float4 ra[4], rb[4];

    auto ldg = [&](const float* A, int lda, const float* B, int ldb, int k0) {
        #pragma unroll
        for (int i = 0; i < 4; i++) {
            int row = l_row + i * 32;
            ra[i] = *(const float4*)(A + (size_t)(bm + row) * lda + k0 + l_col);
            rb[i] = *(const float4*)(B + (size_t)(bn + row) * ldb + k0 + l_col);
        }
    };

    auto sts = [&](int buf) {
        uint32_t* a = sA + buf * SA_SZ;
        uint32_t* b = sB + buf * SB_SZ;
        #pragma unroll
        for (int i = 0; i < 4; i++) {
            int row = l_row + i * 32;
            uint4 w;
            w.x = f2tf32(ra[i].x); w.y = f2tf32(ra[i].y);
            w.z = f2tf32(ra[i].z); w.w = f2tf32(ra[i].w);
            *(uint4*)(a + row * PADA + l_col) = w;
            uint4 v;
            v.x = f2tf32(rb[i].x); v.y = f2tf32(rb[i].y);
            v.z = f2tf32(rb[i].z); v.w = f2tf32(rb[i].w);
            *(uint4*)(b + row * PADB + l_col) = v;
        }
    };

    auto compute = [&](int buf) {
        const uint32_t* a = sA + buf * SA_SZ;
        const uint32_t* b = sB + buf * SB_SZ;
        #pragma unroll
        for (int ks = 0; ks < 4; ks++) {
            const int k = ks * 8;
            uint32_t af[4][4], bf[4][2];
            #pragma unroll
            for (int mt = 0; mt < 4; mt++) {
                int r0 = wm + mt * 16;
                af[mt][0] = a[(r0 + g)     * PADA + k + t4];
                af[mt][1] = a[(r0 + g + 8) * PADA + k + t4];
                af[mt][2] = a[(r0 + g)     * PADA + k + t4 + 4];
                af[mt][3] = a[(r0 + g + 8) * PADA + k + t4 + 4];
            }
            #pragma unroll
            for (int nt = 0; nt < 4; nt++) {
                int nb = wn + nt * 8 + g;
                bf[nt][0] = b[nb * PADB + k + t4];
                bf[nt][1] = b[nb * PADB + k + t4 + 4];
            }
            #pragma unroll
            for (int mt = 0; mt < 4; mt++)
                #pragma unroll
                for (int nt = 0; nt < 4; nt++)
                    mma_tf32(acc[mt][nt], af[mt][0], af[mt][1], af[mt][2], af[mt][3],
                             bf[nt][0], bf[nt][1]);
        }
    };

    const int T0 = K0 / BKT;
    const int T1 = K1 / BKT;
    const int T  = T0 + T1;

    auto ldg_t = [&](int t) {
        if (t < T0) ldg(A0, lda0, B0, ldb0, t * BKT);
        else        ldg(A1, lda1, B1, ldb1, (t - T0) * BKT);
    };

    ldg_t(0);
    sts(0);
    __syncthreads();

    for (int t = 0; t < T; t++) {
        const int cur = t & 1;
        if (t + 1 < T) ldg_t(t + 1);
        compute(cur);
        if (t + 1 < T) sts(cur ^ 1);
        __syncthreads();
    }

    // Epilogue
    #pragma unroll
    for (int mt = 0; mt < 4; mt++) {
        #pragma unroll
        for (int nt = 0; nt < 4; nt++) {
            const int row0 = bm + wm + mt * 16 + g;
            const int col0 = bn + wn + nt * 8 + t4 * 2;
            float bv0 = 0.f, bv1 = 0.f;
            if (bias) { bv0 = bias[col0]; bv1 = bias[col0 + 1]; }
            float2 o0 = make_float2(acc[mt][nt][0] + bv0, acc[mt][nt][1] + bv1);
            float2 o1 = make_float2(acc[mt][nt][2] + bv0, acc[mt][nt][3] + bv1);
            *(float2*)(C + (size_t)row0 * ldc + col0)       = o0;
            *(float2*)(C + (size_t)(row0 + 8) * ldc + col0) = o1;
        }
    }
}

// ---------------------------------------------------------------------------
// Repack B_w [E][O][R] -> g_Ball [O][E*R]
// ---------------------------------------------------------------------------
__global__ void prep_ball_kernel(const float* __restrict__ Bw)
{
    int idx = blockIdx.x * blockDim.x + threadIdx.x;   // 0 .. O*ERC-1
    int o = idx >> 7;
    int c = idx & 127;
    g_Ball[idx] = Bw[(size_t)(c >> 4) * OUT_F * RLOR + (size_t)o * RLOR + (c & 15)];
}

// ---------------------------------------------------------------------------
// Router (exact fp32) + top-2 softmax + split-K reduction + scaling.
// Reads KSPLIT partials of si, writes scaled sum into partial 0.
// One warp per token.
// ---------------------------------------------------------------------------
__global__ void router_mask_kernel(const float* __restrict__ x,
                                   const float* __restrict__ Wr,   // [E][IN]
                                   float* __restrict__ si)         // [KSPLIT][BT][ERC]
{
    const int tok  = (blockIdx.x * blockDim.x + threadIdx.x) >> 5;
    const int lane = threadIdx.x & 31;
    if (tok >= BT) return;

    const float* xr = x + (size_t)tok * IN_F;
    float acc[NEXP];
    #pragma unroll
    for (int e = 0; e < NEXP; e++) acc[e] = 0.f;

    for (int k = lane * 4; k < IN_F; k += 128) {
        float4 xv = *(const float4*)(xr + k);
        #pragma unroll
        for (int e = 0; e < NEXP; e++) {
            float4 wv = *(const float4*)(Wr + (size_t)e * IN_F + k);
            acc[e] += xv.x * wv.x + xv.y * wv.y + xv.z * wv.z + xv.w * wv.w;
        }
    }
    #pragma unroll
    for (int e = 0; e < NEXP; e++)
        #pragma unroll
        for (int off = 16; off > 0; off >>= 1)
            acc[e] += __shfl_xor_sync(0xFFFFFFFFu, acc[e], off);

    // top-2 (ties -> lower index, matching jax.lax.top_k)
    int i0 = 0; float v0 = acc[0];
    #pragma unroll
    for (int e = 1; e < NEXP; e++) if (acc[e] > v0) { v0 = acc[e]; i0 = e; }
    int i1 = -1; float v1 = -3.4e38f;
    #pragma unroll
    for (int e = 0; e < NEXP; e++) if (e != i0 && acc[e] > v1) { v1 = acc[e]; i1 = e; }

    const float ex = expf(v1 - v0);          // v0 >= v1
    const float w0 = 1.f / (1.f + ex);
    const float w1 = ex / (1.f + ex);
    // SCALING = LORA_ALPHA / R = 1.0 -> folded

    float* s = si + (size_t)tok * ERC;
    #pragma unroll
    for (int j = 0; j < 4; j++) {
        int c = lane + j * 32;
        int e = c >> 4;
        float f = (e == i0) ? w0 : (e == i1) ? w1 : 0.f;
        float sum = 0.f;
        #pragma unroll
        for (int p = 0; p < KSPLIT; p++)
            sum += si[(size_t)p * BT * ERC + (size_t)tok * ERC + c];
        s[c] = sum * f;
    }
}

// ---------------------------------------------------------------------------
extern "C" void kernel_launch(void* const* d_in, const int* in_sizes, int n_in,
                              void* d_out, int out_size)
{
    const float* x  = (const float*)d_in[0];   // [B,T,IN]
    const float* Wb = (const float*)d_in[1];   // [OUT,IN]
    const float* bb = (const float*)d_in[2];   // [OUT]
    const float* Wr = (const float*)d_in[3];   // [E,IN]
    const float* Aw = (const float*)d_in[4];   // [E,R,IN] == A_all [ERC][IN]
    const float* Bw = (const float*)d_in[5];   // [E,OUT,R]
    float* out = (float*)d_out;

    float *si, *ball;
    cudaGetSymbolAddress((void**)&si,   g_si);
    cudaGetSymbolAddress((void**)&ball, g_Ball);

    cudaFuncSetAttribute(gemm_tf32_kernel,
                         cudaFuncAttributeMaxDynamicSharedMemorySize, SMEM_BYTES);

    // 1) repack B_w
    prep_ball_kernel<<<(OUT_F * ERC) / 256, 256>>>(Bw);

    // 2) si partials = x @ A_all^T   (M=8192, N=128, K=4096, split-K x4)
    dim3 g1(ERC / BN, BT / BM, KSPLIT);
    gemm_tf32_kernel<<<g1, 256, SMEM_BYTES>>>(
        x, IN_F, Aw, IN_F, IN_F / KSPLIT,
        nullptr, 0, nullptr, 0, 0,
        si, ERC, nullptr, (size_t)BT * ERC);

    // 3) router + top-2 softmax + split-K reduce + scale (into partial 0)
    router_mask_kernel<<<BT / 8, 256>>>(x, Wr, si);

    // 4) out = x @ W_base^T (K=4096) + si @ B_all^T (K=128) + b
    dim3 g2(OUT_F / BN, BT / BM, 1);
    gemm_tf32_kernel<<<g2, 256, SMEM_BYTES>>>(
        x, IN_F, Wb, IN_F, IN_F,
        si, ERC, ball, ERC, ERC,
        out, OUT_F, bb, 0);
}

// round 5
// speedup vs baseline: 2.0543x; 1.2455x over previous
#include <cuda_runtime.h>
#include <cstdint>
#include <cstddef>

// Problem shape (fixed by the dataset)
#define BT   8192
#define IN_F 4096
#define OUT_F 4096
#define NEXP 8
#define RLOR 16
#define ERC  128
#define KSPLIT 4

// GEMM tiling
#define BM 128
#define BN 128
#define BKT 32
#define NSTAGE 3
#define PADT 36                      // smem row stride in floats (144B, 16B-aligned)
#define SA_SZ (BM * PADT)            // 4608 floats
#define SB_SZ (BN * PADT)            // 4608 floats
#define STAGE_SZ (SA_SZ + SB_SZ)     // 9216 floats
#define SMEM_BYTES (NSTAGE * STAGE_SZ * 4)   // 110592 B

// Scratch (no device allocation allowed -> __device__ globals)
__device__ float g_si[(size_t)KSPLIT * BT * ERC];   // split-K partials (part 0 = final)
__device__ float g_Ball[(size_t)OUT_F * ERC];       // B_w repacked [O][E*R]

__device__ __forceinline__ uint32_t smem_u32(const void* p) {
    uint32_t a;
    asm("{ .reg .u64 t; cvta.to.shared.u64 t, %1; cvt.u32.u64 %0, t; }" : "=r"(a) : "l"(p));
    return a;
}
__device__ __forceinline__ void cpa16(uint32_t dst, const void* src) {
    asm volatile("cp.async.cg.shared.global [%0], [%1], 16;" :: "r"(dst), "l"(src));
}
#define CPA_COMMIT() asm volatile("cp.async.commit_group;" ::: "memory")
#define CPA_WAIT(n)  asm volatile("cp.async.wait_group %0;" :: "n"(n) : "memory")

__device__ __forceinline__ void mma_tf32(float c[4],
                                         uint32_t a0, uint32_t a1, uint32_t a2, uint32_t a3,
                                         uint32_t b0, uint32_t b1) {
    asm volatile(
        "mma.sync.aligned.m16n8k8.row.col.f32.tf32.tf32.f32 "
        "{%0,%1,%2,%3}, {%4,%5,%6,%7}, {%8,%9}, {%0,%1,%2,%3};"
        : "+f"(c[0]), "+f"(c[1]), "+f"(c[2]), "+f"(c[3])
        : "r"(a0), "r"(a1), "r"(a2), "r"(a3), "r"(b0), "r"(b1));
}

// ---------------------------------------------------------------------------
// Dual-phase TF32 GEMM (cp.async 3-stage):
//   C = A0 @ B0^T (K0) + A1 @ B1^T (K1) + bias
// A row-major [M][lda], B row-major [N][ldb]. Inputs fp32; HW tf32-truncates.
// blockIdx.z = split-K slice (offsets A0/B0 by z*K0 along K, C by z*cpart).
// ---------------------------------------------------------------------------
__global__ __launch_bounds__(256, 2)
void gemm_tf32_kernel(const float* __restrict__ A0, int lda0,
                      const float* __restrict__ B0, int ldb0, int K0,
                      const float* __restrict__ A1, int lda1,
                      const float* __restrict__ B1, int ldb1, int K1,
                      float* __restrict__ C, int ldc,
                      const float* __restrict__ bias,
                      size_t cpart)
{
    extern __shared__ float smem_f[];

    const int z = blockIdx.z;
    A0 += (size_t)z * K0;
    B0 += (size_t)z * K0;
    C  += (size_t)z * cpart;

    const int tid  = threadIdx.x;
    const int bm   = blockIdx.y * BM;
    const int bn   = blockIdx.x * BN;
    const int warp = tid >> 5;
    const int lane = tid & 31;
    const int wm   = (warp >> 2) * 64;   // 2 warps along M
    const int wn   = (warp & 3) * 32;    // 4 warps along N
    const int g    = lane >> 2;
    const int t4   = lane & 3;

    float acc[4][4][4];
    #pragma unroll
    for (int i = 0; i < 4; i++)
        #pragma unroll
        for (int j = 0; j < 4; j++)
            #pragma unroll
            for (int v = 0; v < 4; v++) acc[i][j][v] = 0.f;

    // Loader indexing: 4 slabs of 32 rows, 8 threads x 16B across a 32-float row
    const int l_row = tid >> 3;            // 0..31
    const int l_col = (tid & 7) * 4;       // 0..28

    const uint32_t smem_base = smem_u32(smem_f);
    // per-thread smem write addresses (stage 0), in bytes
    const uint32_t wA0 = smem_base + (l_row * PADT + l_col) * 4;
    const uint32_t wB0 = wA0 + SA_SZ * 4;

    const int T0 = K0 / BKT;
    const int T1 = K1 / BKT;
    const int T  = T0 + T1;

    auto load_chunk = [&](int c) {
        const uint32_t st = (uint32_t)(c % NSTAGE) * (STAGE_SZ * 4);
        const float *A, *B; int lda, ldb, k0;
        if (c < T0) { A = A0; lda = lda0; B = B0; ldb = ldb0; k0 = c * BKT; }
        else        { A = A1; lda = lda1; B = B1; ldb = ldb1; k0 = (c - T0) * BKT; }
        const float* ap = A + (size_t)(bm + l_row) * lda + k0 + l_col;
        const float* bp = B + (size_t)(bn + l_row) * ldb + k0 + l_col;
        #pragma unroll
        for (int i = 0; i < 4; i++) {
            cpa16(st + wA0 + i * (32 * PADT * 4), ap + (size_t)(i * 32) * lda);
            cpa16(st + wB0 + i * (32 * PADT * 4), bp + (size_t)(i * 32) * ldb);
        }
    };

    auto compute = [&](int buf) {
        const uint32_t* a = (const uint32_t*)(smem_f + buf * STAGE_SZ);
        const uint32_t* b = a + SA_SZ;
        #pragma unroll
        for (int ks = 0; ks < 4; ks++) {
            const int k = ks * 8;
            uint32_t af[4][4], bf[4][2];
            #pragma unroll
            for (int mt = 0; mt < 4; mt++) {
                int r0 = wm + mt * 16;
                af[mt][0] = a[(r0 + g)     * PADT + k + t4];
                af[mt][1] = a[(r0 + g + 8) * PADT + k + t4];
                af[mt][2] = a[(r0 + g)     * PADT + k + t4 + 4];
                af[mt][3] = a[(r0 + g + 8) * PADT + k + t4 + 4];
            }
            #pragma unroll
            for (int nt = 0; nt < 4; nt++) {
                int nb = wn + nt * 8 + g;
                bf[nt][0] = b[nb * PADT + k + t4];
                bf[nt][1] = b[nb * PADT + k + t4 + 4];
            }
            #pragma unroll
            for (int mt = 0; mt < 4; mt++)
                #pragma unroll
                for (int nt = 0; nt < 4; nt++)
                    mma_tf32(acc[mt][nt], af[mt][0], af[mt][1], af[mt][2], af[mt][3],
                             bf[nt][0], bf[nt][1]);
        }
    };

    // prologue: stages 0..NSTAGE-2
    #pragma unroll
    for (int p = 0; p < NSTAGE - 1; p++) {
        if (p < T) load_chunk(p);
        CPA_COMMIT();
    }

    for (int t = 0; t < T; t++) {
        CPA_WAIT(NSTAGE - 2);        // chunk t resident
        __syncthreads();
        compute(t % NSTAGE);
        __syncthreads();             // all warps done with stage t%NSTAGE
        if (t + NSTAGE - 1 < T) load_chunk(t + NSTAGE - 1);
        CPA_COMMIT();
    }

    // Epilogue
    #pragma unroll
    for (int mt = 0; mt < 4; mt++) {
        #pragma unroll
        for (int nt = 0; nt < 4; nt++) {
            const int row0 = bm + wm + mt * 16 + g;
            const int col0 = bn + wn + nt * 8 + t4 * 2;
            float bv0 = 0.f, bv1 = 0.f;
            if (bias) { bv0 = bias[col0]; bv1 = bias[col0 + 1]; }
            float2 o0 = make_float2(acc[mt][nt][0] + bv0, acc[mt][nt][1] + bv1);
            float2 o1 = make_float2(acc[mt][nt][2] + bv0, acc[mt][nt][3] + bv1);
            *(float2*)(C + (size_t)row0 * ldc + col0)       = o0;
            *(float2*)(C + (size_t)(row0 + 8) * ldc + col0) = o1;
        }
    }
}

// ---------------------------------------------------------------------------
// Repack B_w [E][O][R] -> g_Ball [O][E*R]
// ---------------------------------------------------------------------------
__global__ void prep_ball_kernel(const float* __restrict__ Bw)
{
    int idx = blockIdx.x * blockDim.x + threadIdx.x;
    int o = idx >> 7;
    int c = idx & 127;
    g_Ball[idx] = Bw[(size_t)(c >> 4) * OUT_F * RLOR + (size_t)o * RLOR + (c & 15)];
}

// ---------------------------------------------------------------------------
// Router (exact fp32) + top-2 softmax + split-K reduction + scaling.
// ---------------------------------------------------------------------------
__global__ void router_mask_kernel(const float* __restrict__ x,
                                   const float* __restrict__ Wr,
                                   float* __restrict__ si)
{
    const int tok  = (blockIdx.x * blockDim.x + threadIdx.x) >> 5;
    const int lane = threadIdx.x & 31;
    if (tok >= BT) return;

    const float* xr = x + (size_t)tok * IN_F;
    float acc[NEXP];
    #pragma unroll
    for (int e = 0; e < NEXP; e++) acc[e] = 0.f;

    for (int k = lane * 4; k < IN_F; k += 128) {
        float4 xv = *(const float4*)(xr + k);
        #pragma unroll
        for (int e = 0; e < NEXP; e++) {
            float4 wv = *(const float4*)(Wr + (size_t)e * IN_F + k);
            acc[e] += xv.x * wv.x + xv.y * wv.y + xv.z * wv.z + xv.w * wv.w;
        }
    }
    #pragma unroll
    for (int e = 0; e < NEXP; e++)
        #pragma unroll
        for (int off = 16; off > 0; off >>= 1)
            acc[e] += __shfl_xor_sync(0xFFFFFFFFu, acc[e], off);

    int i0 = 0; float v0 = acc[0];
    #pragma unroll
    for (int e = 1; e < NEXP; e++) if (acc[e] > v0) { v0 = acc[e]; i0 = e; }
    int i1 = -1; float v1 = -3.4e38f;
    #pragma unroll
    for (int e = 0; e < NEXP; e++) if (e != i0 && acc[e] > v1) { v1 = acc[e]; i1 = e; }

    const float ex = expf(v1 - v0);
    const float w0 = 1.f / (1.f + ex);
    const float w1 = ex / (1.f + ex);

    float* s = si + (size_t)tok * ERC;
    #pragma unroll
    for (int j = 0; j < 4; j++) {
        int c = lane + j * 32;
        int e = c >> 4;
        float f = (e == i0) ? w0 : (e == i1) ? w1 : 0.f;
        float sum = 0.f;
        #pragma unroll
        for (int p = 0; p < KSPLIT; p++)
            sum += si[(size_t)p * BT * ERC + (size_t)tok * ERC + c];
        s[c] = sum * f;
    }
}

// ---------------------------------------------------------------------------
extern "C" void kernel_launch(void* const* d_in, const int* in_sizes, int n_in,
                              void* d_out, int out_size)
{
    const float* x  = (const float*)d_in[0];   // [B,T,IN]
    const float* Wb = (const float*)d_in[1];   // [OUT,IN]
    const float* bb = (const float*)d_in[2];   // [OUT]
    const float* Wr = (const float*)d_in[3];   // [E,IN]
    const float* Aw = (const float*)d_in[4];   // [E,R,IN] == A_all [ERC][IN]
    const float* Bw = (const float*)d_in[5];   // [E,OUT,R]
    float* out = (float*)d_out;

    float *si, *ball;
    cudaGetSymbolAddress((void**)&si,   g_si);
    cudaGetSymbolAddress((void**)&ball, g_Ball);

    cudaFuncSetAttribute(gemm_tf32_kernel,
                         cudaFuncAttributeMaxDynamicSharedMemorySize, SMEM_BYTES);

    // 1) repack B_w
    prep_ball_kernel<<<(OUT_F * ERC) / 256, 256>>>(Bw);

    // 2) si partials = x @ A_all^T   (M=8192, N=128, K=4096, split-K x4)
    dim3 g1(ERC / BN, BT / BM, KSPLIT);
    gemm_tf32_kernel<<<g1, 256, SMEM_BYTES>>>(
        x, IN_F, Aw, IN_F, IN_F / KSPLIT,
        nullptr, 0, nullptr, 0, 0,
        si, ERC, nullptr, (size_t)BT * ERC);

    // 3) router + top-2 softmax + split-K reduce + scale (into partial 0)
    router_mask_kernel<<<BT / 8, 256>>>(x, Wr, si);

    // 4) out = x @ W_base^T (K=4096) + si @ B_all^T (K=128) + b
    dim3 g2(OUT_F / BN, BT / BM, 1);
    gemm_tf32_kernel<<<g2, 256, SMEM_BYTES>>>(
        x, IN_F, Wb, IN_F, IN_F,
        si, ERC, ball, ERC, ERC,
        out, OUT_F, bb, 0);
}

// round 6
// speedup vs baseline: 3.6017x; 1.7533x over previous
#include <cuda_runtime.h>
#include <cuda_fp16.h>
#include <cstdint>
#include <cstddef>

// Problem shape (fixed by the dataset)
#define BT   8192
#define IN_F 4096
#define OUT_F 4096
#define NEXP 8
#define RLOR 16
#define ERC  128
#define KSPLIT 4

// GEMM tiling (fp16 operands, fp32 accum)
#define BM 128
#define BN 128
#define BKT 64                        // K elements (halves) per chunk = 128B rows
#define NSTAGE 3
#define PADH 72                       // smem row stride in halves (144B)
#define PADU 36                       // same, in u32
#define TILE_B (BM * PADH * 2)        // 18432 B per tile
#define STAGE_B (2 * TILE_B)          // 36864 B per stage
#define SMEM_BYTES (NSTAGE * STAGE_B) // 110592 B

// Scratch (no device allocation allowed -> __device__ globals)
__device__ __half g_xh [(size_t)BT * IN_F];         // 64 MB: x in fp16
__device__ __half g_wbh[(size_t)OUT_F * IN_F];      // 32 MB: W_base in fp16
__device__ __half g_awh[(size_t)ERC * IN_F];        // 1 MB:  A_all in fp16
__device__ __half g_ballh[(size_t)OUT_F * ERC];     // 1 MB:  B_all repacked fp16
__device__ float  g_si [(size_t)KSPLIT * BT * ERC]; // 16 MB: split-K fp32 partials
__device__ __half g_sih[(size_t)BT * ERC];          // 2 MB:  scaled si in fp16

__device__ __forceinline__ uint32_t smem_u32(const void* p) {
    uint32_t a;
    asm("{ .reg .u64 t; cvta.to.shared.u64 t, %1; cvt.u32.u64 %0, t; }" : "=r"(a) : "l"(p));
    return a;
}
__device__ __forceinline__ void cpa16(uint32_t dst, const void* src) {
    asm volatile("cp.async.cg.shared.global [%0], [%1], 16;" :: "r"(dst), "l"(src));
}
#define CPA_COMMIT() asm volatile("cp.async.commit_group;" ::: "memory")
#define CPA_WAIT(n)  asm volatile("cp.async.wait_group %0;" :: "n"(n) : "memory")

__device__ __forceinline__ void mma_f16(float c[4],
                                        uint32_t a0, uint32_t a1, uint32_t a2, uint32_t a3,
                                        uint32_t b0, uint32_t b1) {
    asm volatile(
        "mma.sync.aligned.m16n8k16.row.col.f32.f16.f16.f32 "
        "{%0,%1,%2,%3}, {%4,%5,%6,%7}, {%8,%9}, {%0,%1,%2,%3};"
        : "+f"(c[0]), "+f"(c[1]), "+f"(c[2]), "+f"(c[3])
        : "r"(a0), "r"(a1), "r"(a2), "r"(a3), "r"(b0), "r"(b1));
}

// ---------------------------------------------------------------------------
// Dual-phase FP16 GEMM (cp.async 3-stage, single barrier per chunk):
//   C = A0 @ B0^T (K0) + A1 @ B1^T (K1) + bias   (fp32 accumulate/output)
// A row-major [M][lda], B row-major [N][ldb], lda/ldb in halves.
// blockIdx.z = split-K slice (offsets A0/B0 by z*K0 along K, C by z*cpart).
// ---------------------------------------------------------------------------
__global__ __launch_bounds__(256, 2)
void gemm_f16_kernel(const __half* __restrict__ A0, int lda0,
                     const __half* __restrict__ B0, int ldb0, int K0,
                     const __half* __restrict__ A1, int lda1,
                     const __half* __restrict__ B1, int ldb1, int K1,
                     float* __restrict__ C, int ldc,
                     const float* __restrict__ bias,
                     size_t cpart)
{
    extern __shared__ char smem_raw[];

    const int z = blockIdx.z;
    A0 += (size_t)z * K0;
    B0 += (size_t)z * K0;
    C  += (size_t)z * cpart;

    const int tid  = threadIdx.x;
    const int bm   = blockIdx.y * BM;
    const int bn   = blockIdx.x * BN;
    const int warp = tid >> 5;
    const int lane = tid & 31;
    const int wm   = (warp >> 2) * 64;   // 2 warps along M
    const int wn   = (warp & 3) * 32;    // 4 warps along N
    const int g    = lane >> 2;
    const int t4   = lane & 3;

    float acc[4][4][4];
    #pragma unroll
    for (int i = 0; i < 4; i++)
        #pragma unroll
        for (int j = 0; j < 4; j++)
            #pragma unroll
            for (int v = 0; v < 4; v++) acc[i][j][v] = 0.f;

    // Loader: 4 slabs of 32 rows; 8 threads x 16B (8 halves) across a 64-half row
    const int l_row  = tid >> 3;           // 0..31
    const int l_colh = (tid & 7) * 8;      // 0..56 halves

    const uint32_t smem_base = smem_u32(smem_raw);
    const uint32_t wA0 = smem_base + (l_row * PADH + l_colh) * 2;
    const uint32_t wB0 = wA0 + TILE_B;

    const int T0 = K0 / BKT;
    const int T1 = K1 / BKT;
    const int T  = T0 + T1;

    auto load_chunk = [&](int c) {
        const uint32_t st = (uint32_t)(c % NSTAGE) * STAGE_B;
        const __half *A, *B; int lda, ldb, k0;
        if (c < T0) { A = A0; lda = lda0; B = B0; ldb = ldb0; k0 = c * BKT; }
        else        { A = A1; lda = lda1; B = B1; ldb = ldb1; k0 = (c - T0) * BKT; }
        const __half* ap = A + (size_t)(bm + l_row) * lda + k0 + l_colh;
        const __half* bp = B + (size_t)(bn + l_row) * ldb + k0 + l_colh;
        #pragma unroll
        for (int i = 0; i < 4; i++) {
            cpa16(st + wA0 + i * (32 * PADH * 2), ap + (size_t)(i * 32) * lda);
            cpa16(st + wB0 + i * (32 * PADH * 2), bp + (size_t)(i * 32) * ldb);
        }
    };

    auto compute = [&](int buf) {
        const uint32_t* a = (const uint32_t*)(smem_raw + buf * STAGE_B);
        const uint32_t* b = a + BM * PADU;
        #pragma unroll
        for (int ks = 0; ks < 4; ks++) {          // each ks covers k16
            const int kk = ks * 8;                 // u32 offset (16 halves)
            uint32_t af[4][4], bf[4][2];
            #pragma unroll
            for (int mt = 0; mt < 4; mt++) {
                int r0 = wm + mt * 16;
                af[mt][0] = a[(r0 + g)     * PADU + kk + t4];
                af[mt][1] = a[(r0 + g + 8) * PADU + kk + t4];
                af[mt][2] = a[(r0 + g)     * PADU + kk + t4 + 4];
                af[mt][3] = a[(r0 + g + 8) * PADU + kk + t4 + 4];
            }
            #pragma unroll
            for (int nt = 0; nt < 4; nt++) {
                int nb = wn + nt * 8 + g;
                bf[nt][0] = b[nb * PADU + kk + t4];
                bf[nt][1] = b[nb * PADU + kk + t4 + 4];
            }
            #pragma unroll
            for (int mt = 0; mt < 4; mt++)
                #pragma unroll
                for (int nt = 0; nt < 4; nt++)
                    mma_f16(acc[mt][nt], af[mt][0], af[mt][1], af[mt][2], af[mt][3],
                            bf[nt][0], bf[nt][1]);
        }
    };

    // prologue: stages 0..NSTAGE-2
    #pragma unroll
    for (int p = 0; p < NSTAGE - 1; p++) {
        if (p < T) load_chunk(p);
        CPA_COMMIT();
    }

    for (int t = 0; t < T; t++) {
        CPA_WAIT(NSTAGE - 2);       // chunk t landed (this thread's groups)
        __syncthreads();            // visibility + all warps done with stage (t-1)%NSTAGE
        if (t + NSTAGE - 1 < T) load_chunk(t + NSTAGE - 1);
        CPA_COMMIT();
        compute(t % NSTAGE);
    }

    // Epilogue (fp32)
    #pragma unroll
    for (int mt = 0; mt < 4; mt++) {
        #pragma unroll
        for (int nt = 0; nt < 4; nt++) {
            const int row0 = bm + wm + mt * 16 + g;
            const int col0 = bn + wn + nt * 8 + t4 * 2;
            float bv0 = 0.f, bv1 = 0.f;
            if (bias) { bv0 = bias[col0]; bv1 = bias[col0 + 1]; }
            float2 o0 = make_float2(acc[mt][nt][0] + bv0, acc[mt][nt][1] + bv1);
            float2 o1 = make_float2(acc[mt][nt][2] + bv0, acc[mt][nt][3] + bv1);
            *(float2*)(C + (size_t)row0 * ldc + col0)       = o0;
            *(float2*)(C + (size_t)(row0 + 8) * ldc + col0) = o1;
        }
    }
}

// ---------------------------------------------------------------------------
// f32 -> f16 conversion (round-to-nearest), 8 elements per thread
// ---------------------------------------------------------------------------
__global__ void f2h_kernel(const float* __restrict__ in, __half* __restrict__ out)
{
    const size_t i = ((size_t)blockIdx.x * blockDim.x + threadIdx.x) * 8;
    float4 v0 = *(const float4*)(in + i);
    float4 v1 = *(const float4*)(in + i + 4);
    __half2 h[4];
    h[0] = __float22half2_rn(make_float2(v0.x, v0.y));
    h[1] = __float22half2_rn(make_float2(v0.z, v0.w));
    h[2] = __float22half2_rn(make_float2(v1.x, v1.y));
    h[3] = __float22half2_rn(make_float2(v1.z, v1.w));
    *(uint4*)(out + i) = *(uint4*)h;
}

// ---------------------------------------------------------------------------
// Repack B_w [E][O][R] -> g_ballh [O][E*R] (fp16)
// ---------------------------------------------------------------------------
__global__ void prep_ball_kernel(const float* __restrict__ Bw)
{
    int idx = blockIdx.x * blockDim.x + threadIdx.x;
    int o = idx >> 7;
    int c = idx & 127;
    g_ballh[idx] = __float2half_rn(
        Bw[(size_t)(c >> 4) * OUT_F * RLOR + (size_t)o * RLOR + (c & 15)]);
}

// ---------------------------------------------------------------------------
// Router (exact fp32 on original x) + top-2 softmax + split-K reduce + scale,
// writes fp16 si. One warp per token.
// ---------------------------------------------------------------------------
__global__ void router_mask_kernel(const float* __restrict__ x,
                                   const float* __restrict__ Wr)
{
    const int tok  = (blockIdx.x * blockDim.x + threadIdx.x) >> 5;
    const int lane = threadIdx.x & 31;
    if (tok >= BT) return;

    const float* xr = x + (size_t)tok * IN_F;
    float acc[NEXP];
    #pragma unroll
    for (int e = 0; e < NEXP; e++) acc[e] = 0.f;

    for (int k = lane * 4; k < IN_F; k += 128) {
        float4 xv = *(const float4*)(xr + k);
        #pragma unroll
        for (int e = 0; e < NEXP; e++) {
            float4 wv = *(const float4*)(Wr + (size_t)e * IN_F + k);
            acc[e] += xv.x * wv.x + xv.y * wv.y + xv.z * wv.z + xv.w * wv.w;
        }
    }
    #pragma unroll
    for (int e = 0; e < NEXP; e++)
        #pragma unroll
        for (int off = 16; off > 0; off >>= 1)
            acc[e] += __shfl_xor_sync(0xFFFFFFFFu, acc[e], off);

    int i0 = 0; float v0 = acc[0];
    #pragma unroll
    for (int e = 1; e < NEXP; e++) if (acc[e] > v0) { v0 = acc[e]; i0 = e; }
    int i1 = -1; float v1 = -3.4e38f;
    #pragma unroll
    for (int e = 0; e < NEXP; e++) if (e != i0 && acc[e] > v1) { v1 = acc[e]; i1 = e; }

    const float ex = expf(v1 - v0);
    const float w0 = 1.f / (1.f + ex);
    const float w1 = ex / (1.f + ex);

    #pragma unroll
    for (int j = 0; j < 4; j++) {
        int c = lane + j * 32;
        int e = c >> 4;
        float f = (e == i0) ? w0 : (e == i1) ? w1 : 0.f;
        float sum = 0.f;
        #pragma unroll
        for (int p = 0; p < KSPLIT; p++)
            sum += g_si[(size_t)p * BT * ERC + (size_t)tok * ERC + c];
        g_sih[(size_t)tok * ERC + c] = __float2half_rn(sum * f);
    }
}

// ---------------------------------------------------------------------------
extern "C" void kernel_launch(void* const* d_in, const int* in_sizes, int n_in,
                              void* d_out, int out_size)
{
    const float* x  = (const float*)d_in[0];   // [B,T,IN]
    const float* Wb = (const float*)d_in[1];   // [OUT,IN]
    const float* bb = (const float*)d_in[2];   // [OUT]
    const float* Wr = (const float*)d_in[3];   // [E,IN]
    const float* Aw = (const float*)d_in[4];   // [E,R,IN] == A_all [ERC][IN]
    const float* Bw = (const float*)d_in[5];   // [E,OUT,R]
    float* out = (float*)d_out;

    __half *xh, *wbh, *awh;
    float* si;
    cudaGetSymbolAddress((void**)&xh,  g_xh);
    cudaGetSymbolAddress((void**)&wbh, g_wbh);
    cudaGetSymbolAddress((void**)&awh, g_awh);
    cudaGetSymbolAddress((void**)&si,  g_si);
    __half *sih, *ballh;
    cudaGetSymbolAddress((void**)&sih,   g_sih);
    cudaGetSymbolAddress((void**)&ballh, g_ballh);

    cudaFuncSetAttribute(gemm_f16_kernel,
                         cudaFuncAttributeMaxDynamicSharedMemorySize, SMEM_BYTES);

    // 0) fp32 -> fp16 conversions (round-to-nearest)
    f2h_kernel<<<(size_t)BT * IN_F / 2048, 256>>>(x, xh);
    f2h_kernel<<<(size_t)OUT_F * IN_F / 2048, 256>>>(Wb, wbh);
    f2h_kernel<<<(size_t)ERC * IN_F / 2048, 256>>>(Aw, awh);
    prep_ball_kernel<<<(OUT_F * ERC) / 256, 256>>>(Bw);

    // 1) si partials = x @ A_all^T   (M=8192, N=128, K=4096, split-K x4)
    dim3 g1(ERC / BN, BT / BM, KSPLIT);
    gemm_f16_kernel<<<g1, 256, SMEM_BYTES>>>(
        xh, IN_F, awh, IN_F, IN_F / KSPLIT,
        nullptr, 0, nullptr, 0, 0,
        si, ERC, nullptr, (size_t)BT * ERC);

    // 2) router + top-2 softmax + split-K reduce + scale -> fp16 si
    router_mask_kernel<<<BT / 8, 256>>>(x, Wr);

    // 3) out = x @ W_base^T (K=4096) + si @ B_all^T (K=128) + b
    dim3 g2(OUT_F / BN, BT / BM, 1);
    gemm_f16_kernel<<<g2, 256, SMEM_BYTES>>>(
        xh, IN_F, wbh, IN_F, IN_F,
        sih, ERC, ballh, ERC, ERC,
        out, OUT_F, bb, 0);
}

// round 7
// speedup vs baseline: 3.9656x; 1.1010x over previous
#include <cuda_runtime.h>
#include <cuda_fp16.h>
#include <cstdint>
#include <cstddef>

// Problem shape (fixed by the dataset)
#define BT   8192
#define IN_F 4096
#define OUT_F 4096
#define NEXP 8
#define RLOR 16
#define ERC  128
#define KSPLIT 4

// GEMM tiling (fp16 operands, fp32 accum)
#define BM 128
#define BN 128
#define BKT 64                        // K halves per chunk = 128B rows
#define NSTAGE 3
#define PADH 72                       // smem row stride in halves (144B)
#define TILE_B (BM * PADH * 2)        // 18432 B per tile
#define STAGE_B (2 * TILE_B)          // 36864 B per stage
#define SMEM_BYTES (NSTAGE * STAGE_B) // 110592 B

// Scratch (no device allocation allowed -> __device__ globals)
__device__ __half g_xh [(size_t)BT * IN_F];         // 64 MB: x in fp16
__device__ __half g_wbh[(size_t)OUT_F * IN_F];      // 32 MB: W_base in fp16
__device__ __half g_awh[(size_t)ERC * IN_F];        // 1 MB:  A_all in fp16
__device__ __half g_ballh[(size_t)OUT_F * ERC];     // 1 MB:  B_all repacked fp16
__device__ float  g_si [(size_t)KSPLIT * BT * ERC]; // 16 MB: split-K fp32 partials
__device__ __half g_sih[(size_t)BT * ERC];          // 2 MB:  scaled si in fp16

__device__ __forceinline__ uint32_t smem_u32(const void* p) {
    uint32_t a;
    asm("{ .reg .u64 t; cvta.to.shared.u64 t, %1; cvt.u32.u64 %0, t; }" : "=r"(a) : "l"(p));
    return a;
}
__device__ __forceinline__ void cpa16(uint32_t dst, const void* src) {
    asm volatile("cp.async.cg.shared.global [%0], [%1], 16;" :: "r"(dst), "l"(src));
}
#define CPA_COMMIT() asm volatile("cp.async.commit_group;" ::: "memory")
#define CPA_WAIT(n)  asm volatile("cp.async.wait_group %0;" :: "n"(n) : "memory")

__device__ __forceinline__ void ldsm_x4(uint32_t& r0, uint32_t& r1,
                                        uint32_t& r2, uint32_t& r3, uint32_t addr) {
    asm volatile("ldmatrix.sync.aligned.m8n8.x4.shared.b16 {%0,%1,%2,%3}, [%4];"
                 : "=r"(r0), "=r"(r1), "=r"(r2), "=r"(r3) : "r"(addr));
}

__device__ __forceinline__ void mma_f16(float c[4],
                                        uint32_t a0, uint32_t a1, uint32_t a2, uint32_t a3,
                                        uint32_t b0, uint32_t b1) {
    asm volatile(
        "mma.sync.aligned.m16n8k16.row.col.f32.f16.f16.f32 "
        "{%0,%1,%2,%3}, {%4,%5,%6,%7}, {%8,%9}, {%0,%1,%2,%3};"
        : "+f"(c[0]), "+f"(c[1]), "+f"(c[2]), "+f"(c[3])
        : "r"(a0), "r"(a1), "r"(a2), "r"(a3), "r"(b0), "r"(b1));
}

// ---------------------------------------------------------------------------
// Dual-phase FP16 GEMM (cp.async 3-stage, ldmatrix fragments):
//   C = A0 @ B0^T (K0) + A1 @ B1^T (K1) + bias   (fp32 accumulate/output)
// A row-major [M][lda], B row-major [N][ldb], lda/ldb in halves.
// blockIdx.z = split-K slice (offsets A0/B0 by z*K0 along K, C by z*cpart).
// ---------------------------------------------------------------------------
__global__ __launch_bounds__(256, 2)
void gemm_f16_kernel(const __half* __restrict__ A0, int lda0,
                     const __half* __restrict__ B0, int ldb0, int K0,
                     const __half* __restrict__ A1, int lda1,
                     const __half* __restrict__ B1, int ldb1, int K1,
                     float* __restrict__ C, int ldc,
                     const float* __restrict__ bias,
                     size_t cpart)
{
    extern __shared__ char smem_raw[];

    const int z = blockIdx.z;
    A0 += (size_t)z * K0;
    B0 += (size_t)z * K0;
    C  += (size_t)z * cpart;

    const int tid  = threadIdx.x;
    const int bm   = blockIdx.y * BM;
    const int bn   = blockIdx.x * BN;
    const int warp = tid >> 5;
    const int lane = tid & 31;
    const int wm   = (warp >> 2) * 64;   // 2 warps along M
    const int wn   = (warp & 3) * 32;    // 4 warps along N
    const int g    = lane >> 2;
    const int t4   = lane & 3;

    float acc[4][4][4];
    #pragma unroll
    for (int i = 0; i < 4; i++)
        #pragma unroll
        for (int j = 0; j < 4; j++)
            #pragma unroll
            for (int v = 0; v < 4; v++) acc[i][j][v] = 0.f;

    // Loader: 4 slabs of 32 rows; 8 threads x 16B (8 halves) across a 64-half row
    const int l_row  = tid >> 3;           // 0..31
    const int l_colh = (tid & 7) * 8;      // 0..56 halves

    const uint32_t smem_base = smem_u32(smem_raw);
    const uint32_t wA0 = smem_base + (l_row * PADH + l_colh) * 2;
    const uint32_t wB0 = wA0 + TILE_B;

    // ldmatrix per-thread row/col selectors
    const int lm_a_row = lane & 15;              // A: rows r0..r0+15
    const int lm_a_k8  = (lane >> 4) * 8;        // A: k half-offset 0 or 8
    const int lm_b_row = ((lane >> 4) & 1) * 8 + (lane & 7);  // B: n row within 16
    const int lm_b_k8  = ((lane >> 3) & 1) * 8;  // B: k half-offset 0 or 8

    const int T0 = K0 / BKT;
    const int T1 = K1 / BKT;
    const int T  = T0 + T1;

    auto load_chunk = [&](int c) {
        const uint32_t st = (uint32_t)(c % NSTAGE) * STAGE_B;
        const __half *A, *B; int lda, ldb, k0;
        if (c < T0) { A = A0; lda = lda0; B = B0; ldb = ldb0; k0 = c * BKT; }
        else        { A = A1; lda = lda1; B = B1; ldb = ldb1; k0 = (c - T0) * BKT; }
        const __half* ap = A + (size_t)(bm + l_row) * lda + k0 + l_colh;
        const __half* bp = B + (size_t)(bn + l_row) * ldb + k0 + l_colh;
        #pragma unroll
        for (int i = 0; i < 4; i++) {
            cpa16(st + wA0 + i * (32 * PADH * 2), ap + (size_t)(i * 32) * lda);
            cpa16(st + wB0 + i * (32 * PADH * 2), bp + (size_t)(i * 32) * ldb);
        }
    };

    auto compute = [&](int buf) {
        const uint32_t aB = smem_base + (uint32_t)buf * STAGE_B;
        const uint32_t bB = aB + TILE_B;
        #pragma unroll
        for (int ks = 0; ks < 4; ks++) {          // each ks = one k16 step
            const int kh = ks * 16;                // half offset
            uint32_t af[4][4], bf[4][2];
            #pragma unroll
            for (int mt = 0; mt < 4; mt++) {
                const uint32_t ad = aB +
                    ((wm + mt * 16 + lm_a_row) * PADH + kh + lm_a_k8) * 2;
                ldsm_x4(af[mt][0], af[mt][1], af[mt][2], af[mt][3], ad);
            }
            #pragma unroll
            for (int pr = 0; pr < 2; pr++) {
                const uint32_t bd = bB +
                    ((wn + pr * 16 + lm_b_row) * PADH + kh + lm_b_k8) * 2;
                ldsm_x4(bf[2 * pr][0], bf[2 * pr][1],
                        bf[2 * pr + 1][0], bf[2 * pr + 1][1], bd);
            }
            #pragma unroll
            for (int mt = 0; mt < 4; mt++)
                #pragma unroll
                for (int nt = 0; nt < 4; nt++)
                    mma_f16(acc[mt][nt], af[mt][0], af[mt][1], af[mt][2], af[mt][3],
                            bf[nt][0], bf[nt][1]);
        }
    };

    // prologue: stages 0..NSTAGE-2
    #pragma unroll
    for (int p = 0; p < NSTAGE - 1; p++) {
        if (p < T) load_chunk(p);
        CPA_COMMIT();
    }

    for (int t = 0; t < T; t++) {
        CPA_WAIT(NSTAGE - 2);       // chunk t landed
        __syncthreads();            // visibility + stage reuse guard
        if (t + NSTAGE - 1 < T) load_chunk(t + NSTAGE - 1);
        CPA_COMMIT();
        compute(t % NSTAGE);
    }

    // Epilogue (fp32)
    #pragma unroll
    for (int mt = 0; mt < 4; mt++) {
        #pragma unroll
        for (int nt = 0; nt < 4; nt++) {
            const int row0 = bm + wm + mt * 16 + g;
            const int col0 = bn + wn + nt * 8 + t4 * 2;
            float bv0 = 0.f, bv1 = 0.f;
            if (bias) { bv0 = bias[col0]; bv1 = bias[col0 + 1]; }
            float2 o0 = make_float2(acc[mt][nt][0] + bv0, acc[mt][nt][1] + bv1);
            float2 o1 = make_float2(acc[mt][nt][2] + bv0, acc[mt][nt][3] + bv1);
            *(float2*)(C + (size_t)row0 * ldc + col0)       = o0;
            *(float2*)(C + (size_t)(row0 + 8) * ldc + col0) = o1;
        }
    }
}

// ---------------------------------------------------------------------------
// f32 -> f16 conversion (round-to-nearest), 8 elements per thread
// ---------------------------------------------------------------------------
__global__ void f2h_kernel(const float* __restrict__ in, __half* __restrict__ out)
{
    const size_t i = ((size_t)blockIdx.x * blockDim.x + threadIdx.x) * 8;
    float4 v0 = *(const float4*)(in + i);
    float4 v1 = *(const float4*)(in + i + 4);
    __half2 h[4];
    h[0] = __float22half2_rn(make_float2(v0.x, v0.y));
    h[1] = __float22half2_rn(make_float2(v0.z, v0.w));
    h[2] = __float22half2_rn(make_float2(v1.x, v1.y));
    h[3] = __float22half2_rn(make_float2(v1.z, v1.w));
    *(uint4*)(out + i) = *(uint4*)h;
}

// ---------------------------------------------------------------------------
// Repack B_w [E][O][R] -> g_ballh [O][E*R] (fp16)
// ---------------------------------------------------------------------------
__global__ void prep_ball_kernel(const float* __restrict__ Bw)
{
    int idx = blockIdx.x * blockDim.x + threadIdx.x;
    int o = idx >> 7;
    int c = idx & 127;
    g_ballh[idx] = __float2half_rn(
        Bw[(size_t)(c >> 4) * OUT_F * RLOR + (size_t)o * RLOR + (c & 15)]);
}

// ---------------------------------------------------------------------------
// Router (exact fp32 on original x) + top-2 softmax + split-K reduce + scale,
// writes fp16 si. One warp per token.
// ---------------------------------------------------------------------------
__global__ void router_mask_kernel(const float* __restrict__ x,
                                   const float* __restrict__ Wr)
{
    const int tok  = (blockIdx.x * blockDim.x + threadIdx.x) >> 5;
    const int lane = threadIdx.x & 31;
    if (tok >= BT) return;

    const float* xr = x + (size_t)tok * IN_F;
    float acc[NEXP];
    #pragma unroll
    for (int e = 0; e < NEXP; e++) acc[e] = 0.f;

    for (int k = lane * 4; k < IN_F; k += 128) {
        float4 xv = *(const float4*)(xr + k);
        #pragma unroll
        for (int e = 0; e < NEXP; e++) {
            float4 wv = *(const float4*)(Wr + (size_t)e * IN_F + k);
            acc[e] += xv.x * wv.x + xv.y * wv.y + xv.z * wv.z + xv.w * wv.w;
        }
    }
    #pragma unroll
    for (int e = 0; e < NEXP; e++)
        #pragma unroll
        for (int off = 16; off > 0; off >>= 1)
            acc[e] += __shfl_xor_sync(0xFFFFFFFFu, acc[e], off);

    int i0 = 0; float v0 = acc[0];
    #pragma unroll
    for (int e = 1; e < NEXP; e++) if (acc[e] > v0) { v0 = acc[e]; i0 = e; }
    int i1 = -1; float v1 = -3.4e38f;
    #pragma unroll
    for (int e = 0; e < NEXP; e++) if (e != i0 && acc[e] > v1) { v1 = acc[e]; i1 = e; }

    const float ex = expf(v1 - v0);
    const float w0 = 1.f / (1.f + ex);
    const float w1 = ex / (1.f + ex);

    #pragma unroll
    for (int j = 0; j < 4; j++) {
        int c = lane + j * 32;
        int e = c >> 4;
        float f = (e == i0) ? w0 : (e == i1) ? w1 : 0.f;
        float sum = 0.f;
        #pragma unroll
        for (int p = 0; p < KSPLIT; p++)
            sum += g_si[(size_t)p * BT * ERC + (size_t)tok * ERC + c];
        g_sih[(size_t)tok * ERC + c] = __float2half_rn(sum * f);
    }
}

// ---------------------------------------------------------------------------
extern "C" void kernel_launch(void* const* d_in, const int* in_sizes, int n_in,
                              void* d_out, int out_size)
{
    const float* x  = (const float*)d_in[0];   // [B,T,IN]
    const float* Wb = (const float*)d_in[1];   // [OUT,IN]
    const float* bb = (const float*)d_in[2];   // [OUT]
    const float* Wr = (const float*)d_in[3];   // [E,IN]
    const float* Aw = (const float*)d_in[4];   // [E,R,IN] == A_all [ERC][IN]
    const float* Bw = (const float*)d_in[5];   // [E,OUT,R]
    float* out = (float*)d_out;

    __half *xh, *wbh, *awh, *sih, *ballh;
    float* si;
    cudaGetSymbolAddress((void**)&xh,    g_xh);
    cudaGetSymbolAddress((void**)&wbh,   g_wbh);
    cudaGetSymbolAddress((void**)&awh,   g_awh);
    cudaGetSymbolAddress((void**)&si,    g_si);
    cudaGetSymbolAddress((void**)&sih,   g_sih);
    cudaGetSymbolAddress((void**)&ballh, g_ballh);

    cudaFuncSetAttribute(gemm_f16_kernel,
                         cudaFuncAttributeMaxDynamicSharedMemorySize, SMEM_BYTES);

    // 0) fp32 -> fp16 conversions (round-to-nearest)
    f2h_kernel<<<(size_t)BT * IN_F / 2048, 256>>>(x, xh);
    f2h_kernel<<<(size_t)OUT_F * IN_F / 2048, 256>>>(Wb, wbh);
    f2h_kernel<<<(size_t)ERC * IN_F / 2048, 256>>>(Aw, awh);
    prep_ball_kernel<<<(OUT_F * ERC) / 256, 256>>>(Bw);

    // 1) si partials = x @ A_all^T   (M=8192, N=128, K=4096, split-K x4)
    dim3 g1(ERC / BN, BT / BM, KSPLIT);
    gemm_f16_kernel<<<g1, 256, SMEM_BYTES>>>(
        xh, IN_F, awh, IN_F, IN_F / KSPLIT,
        nullptr, 0, nullptr, 0, 0,
        si, ERC, nullptr, (size_t)BT * ERC);

    // 2) router + top-2 softmax + split-K reduce + scale -> fp16 si
    router_mask_kernel<<<BT / 8, 256>>>(x, Wr);

    // 3) out = x @ W_base^T (K=4096) + si @ B_all^T (K=128) + b
    dim3 g2(OUT_F / BN, BT / BM, 1);
    gemm_f16_kernel<<<g2, 256, SMEM_BYTES>>>(
        xh, IN_F, wbh, IN_F, IN_F,
        sih, ERC, ballh, ERC, ERC,
        out, OUT_F, bb, 0);
}

// round 8
// speedup vs baseline: 3.9660x; 1.0001x over previous
#include <cuda_runtime.h>
#include <cuda_fp16.h>
#include <cstdint>
#include <cstddef>

// Problem shape (fixed by the dataset)
#define BT   8192
#define IN_F 4096
#define OUT_F 4096
#define NEXP 8
#define RLOR 16
#define ERC  128
#define KSPLIT 4

// GEMM tiling (fp16 operands, fp32 accum)
#define BM 128
#define BN 128
#define BKT 64                        // K halves per chunk = 128B rows
#define NSTAGE 3
#define PADH 72                       // smem row stride in halves (144B)
#define TILE_B (BM * PADH * 2)        // 18432 B per tile
#define STAGE_B (2 * TILE_B)          // 36864 B per stage
#define SMEM_BYTES (NSTAGE * STAGE_B) // 110592 B

// Scratch (no device allocation allowed -> __device__ globals)
__device__ __half g_xh [(size_t)BT * IN_F];         // 64 MB: x in fp16
__device__ __half g_wbh[(size_t)OUT_F * IN_F];      // 32 MB: W_base in fp16
__device__ __half g_awh[(size_t)ERC * IN_F];        // 1 MB:  A_all in fp16
__device__ __half g_ballh[(size_t)OUT_F * ERC];     // 1 MB:  B_all repacked fp16
__device__ float  g_si [(size_t)KSPLIT * BT * ERC]; // 16 MB: split-K fp32 partials
__device__ __half g_sih[(size_t)BT * ERC];          // 2 MB:  scaled si in fp16

__device__ __forceinline__ uint32_t smem_u32(const void* p) {
    uint32_t a;
    asm("{ .reg .u64 t; cvta.to.shared.u64 t, %1; cvt.u32.u64 %0, t; }" : "=r"(a) : "l"(p));
    return a;
}
__device__ __forceinline__ void cpa16(uint32_t dst, const void* src) {
    asm volatile("cp.async.cg.shared.global [%0], [%1], 16;" :: "r"(dst), "l"(src));
}
#define CPA_COMMIT() asm volatile("cp.async.commit_group;" ::: "memory")
#define CPA_WAIT(n)  asm volatile("cp.async.wait_group %0;" :: "n"(n) : "memory")

__device__ __forceinline__ void ldsm_x4(uint32_t& r0, uint32_t& r1,
                                        uint32_t& r2, uint32_t& r3, uint32_t addr) {
    asm volatile("ldmatrix.sync.aligned.m8n8.x4.shared.b16 {%0,%1,%2,%3}, [%4];"
                 : "=r"(r0), "=r"(r1), "=r"(r2), "=r"(r3) : "r"(addr));
}

__device__ __forceinline__ void mma_f16(float c[4],
                                        uint32_t a0, uint32_t a1, uint32_t a2, uint32_t a3,
                                        uint32_t b0, uint32_t b1) {
    asm volatile(
        "mma.sync.aligned.m16n8k16.row.col.f32.f16.f16.f32 "
        "{%0,%1,%2,%3}, {%4,%5,%6,%7}, {%8,%9}, {%0,%1,%2,%3};"
        : "+f"(c[0]), "+f"(c[1]), "+f"(c[2]), "+f"(c[3])
        : "r"(a0), "r"(a1), "r"(a2), "r"(a3), "r"(b0), "r"(b1));
}

// ---------------------------------------------------------------------------
// Dual-phase FP16 GEMM (cp.async 3-stage, ldmatrix fragments):
//   C = A0 @ B0^T (K0) + A1 @ B1^T (K1) + bias   (fp32 accumulate/output)
// A row-major [M][lda], B row-major [N][ldb], lda/ldb in halves.
// blockIdx.z = split-K slice (offsets A0/B0 by z*K0 along K, C by z*cpart).
// ---------------------------------------------------------------------------
__global__ __launch_bounds__(256, 2)
void gemm_f16_kernel(const __half* __restrict__ A0, int lda0,
                     const __half* __restrict__ B0, int ldb0, int K0,
                     const __half* __restrict__ A1, int lda1,
                     const __half* __restrict__ B1, int ldb1, int K1,
                     float* __restrict__ C, int ldc,
                     const float* __restrict__ bias,
                     size_t cpart)
{
    extern __shared__ char smem_raw[];

    const int z = blockIdx.z;
    A0 += (size_t)z * K0;
    B0 += (size_t)z * K0;
    C  += (size_t)z * cpart;

    const int tid  = threadIdx.x;
    const int bm   = blockIdx.y * BM;
    const int bn   = blockIdx.x * BN;
    const int warp = tid >> 5;
    const int lane = tid & 31;
    const int wm   = (warp >> 2) * 64;   // 2 warps along M
    const int wn   = (warp & 3) * 32;    // 4 warps along N
    const int g    = lane >> 2;
    const int t4   = lane & 3;

    float acc[4][4][4];
    #pragma unroll
    for (int i = 0; i < 4; i++)
        #pragma unroll
        for (int j = 0; j < 4; j++)
            #pragma unroll
            for (int v = 0; v < 4; v++) acc[i][j][v] = 0.f;

    // Loader: 4 slabs of 32 rows; 8 threads x 16B (8 halves) across a 64-half row
    const int l_row  = tid >> 3;           // 0..31
    const int l_colh = (tid & 7) * 8;      // 0..56 halves

    const uint32_t smem_base = smem_u32(smem_raw);
    const uint32_t wA0 = smem_base + (l_row * PADH + l_colh) * 2;
    const uint32_t wB0 = wA0 + TILE_B;

    // ldmatrix per-thread row/col selectors
    const int lm_a_row = lane & 15;              // A: rows r0..r0+15
    const int lm_a_k8  = (lane >> 4) * 8;        // A: k half-offset 0 or 8
    const int lm_b_row = ((lane >> 4) & 1) * 8 + (lane & 7);  // B: n row within 16
    const int lm_b_k8  = ((lane >> 3) & 1) * 8;  // B: k half-offset 0 or 8

    const int T0 = K0 / BKT;
    const int T1 = K1 / BKT;
    const int T  = T0 + T1;

    auto load_chunk = [&](int c) {
        const uint32_t st = (uint32_t)(c % NSTAGE) * STAGE_B;
        const __half *A, *B; int lda, ldb, k0;
        if (c < T0) { A = A0; lda = lda0; B = B0; ldb = ldb0; k0 = c * BKT; }
        else        { A = A1; lda = lda1; B = B1; ldb = ldb1; k0 = (c - T0) * BKT; }
        const __half* ap = A + (size_t)(bm + l_row) * lda + k0 + l_colh;
        const __half* bp = B + (size_t)(bn + l_row) * ldb + k0 + l_colh;
        #pragma unroll
        for (int i = 0; i < 4; i++) {
            cpa16(st + wA0 + i * (32 * PADH * 2), ap + (size_t)(i * 32) * lda);
            cpa16(st + wB0 + i * (32 * PADH * 2), bp + (size_t)(i * 32) * ldb);
        }
    };

    auto compute = [&](int buf) {
        const uint32_t aB = smem_base + (uint32_t)buf * STAGE_B;
        const uint32_t bB = aB + TILE_B;
        #pragma unroll
        for (int ks = 0; ks < 4; ks++) {          // each ks = one k16 step
            const int kh = ks * 16;                // half offset
            uint32_t af[4][4], bf[4][2];
            #pragma unroll
            for (int mt = 0; mt < 4; mt++) {
                const uint32_t ad = aB +
                    ((wm + mt * 16 + lm_a_row) * PADH + kh + lm_a_k8) * 2;
                ldsm_x4(af[mt][0], af[mt][1], af[mt][2], af[mt][3], ad);
            }
            #pragma unroll
            for (int pr = 0; pr < 2; pr++) {
                const uint32_t bd = bB +
                    ((wn + pr * 16 + lm_b_row) * PADH + kh + lm_b_k8) * 2;
                ldsm_x4(bf[2 * pr][0], bf[2 * pr][1],
                        bf[2 * pr + 1][0], bf[2 * pr + 1][1], bd);
            }
            #pragma unroll
            for (int mt = 0; mt < 4; mt++)
                #pragma unroll
                for (int nt = 0; nt < 4; nt++)
                    mma_f16(acc[mt][nt], af[mt][0], af[mt][1], af[mt][2], af[mt][3],
                            bf[nt][0], bf[nt][1]);
        }
    };

    // prologue: stages 0..NSTAGE-2
    #pragma unroll
    for (int p = 0; p < NSTAGE - 1; p++) {
        if (p < T) load_chunk(p);
        CPA_COMMIT();
    }

    for (int t = 0; t < T; t++) {
        CPA_WAIT(NSTAGE - 2);       // chunk t landed
        __syncthreads();            // visibility + stage reuse guard
        if (t + NSTAGE - 1 < T) load_chunk(t + NSTAGE - 1);
        CPA_COMMIT();
        compute(t % NSTAGE);
    }

    // Epilogue (fp32)
    #pragma unroll
    for (int mt = 0; mt < 4; mt++) {
        #pragma unroll
        for (int nt = 0; nt < 4; nt++) {
            const int row0 = bm + wm + mt * 16 + g;
            const int col0 = bn + wn + nt * 8 + t4 * 2;
            float bv0 = 0.f, bv1 = 0.f;
            if (bias) { bv0 = bias[col0]; bv1 = bias[col0 + 1]; }
            float2 o0 = make_float2(acc[mt][nt][0] + bv0, acc[mt][nt][1] + bv1);
            float2 o1 = make_float2(acc[mt][nt][2] + bv0, acc[mt][nt][3] + bv1);
            *(float2*)(C + (size_t)row0 * ldc + col0)       = o0;
            *(float2*)(C + (size_t)(row0 + 8) * ldc + col0) = o1;
        }
    }
}

// ---------------------------------------------------------------------------
// f32 -> f16 conversion (round-to-nearest), 8 elements per thread
// ---------------------------------------------------------------------------
__global__ void f2h_kernel(const float* __restrict__ in, __half* __restrict__ out)
{
    const size_t i = ((size_t)blockIdx.x * blockDim.x + threadIdx.x) * 8;
    float4 v0 = *(const float4*)(in + i);
    float4 v1 = *(const float4*)(in + i + 4);
    __half2 h[4];
    h[0] = __float22half2_rn(make_float2(v0.x, v0.y));
    h[1] = __float22half2_rn(make_float2(v0.z, v0.w));
    h[2] = __float22half2_rn(make_float2(v1.x, v1.y));
    h[3] = __float22half2_rn(make_float2(v1.z, v1.w));
    *(uint4*)(out + i) = *(uint4*)h;
}

// ---------------------------------------------------------------------------
// Repack B_w [E][O][R] -> g_ballh [O][E*R] (fp16)
// ---------------------------------------------------------------------------
__global__ void prep_ball_kernel(const float* __restrict__ Bw)
{
    int idx = blockIdx.x * blockDim.x + threadIdx.x;
    int o = idx >> 7;
    int c = idx & 127;
    g_ballh[idx] = __float2half_rn(
        Bw[(size_t)(c >> 4) * OUT_F * RLOR + (size_t)o * RLOR + (c & 15)]);
}

// ---------------------------------------------------------------------------
// Router (exact fp32 on original x) + top-2 softmax + split-K reduce + scale,
// writes fp16 si. One warp per token.
// ---------------------------------------------------------------------------
__global__ void router_mask_kernel(const float* __restrict__ x,
                                   const float* __restrict__ Wr)
{
    const int tok  = (blockIdx.x * blockDim.x + threadIdx.x) >> 5;
    const int lane = threadIdx.x & 31;
    if (tok >= BT) return;

    const float* xr = x + (size_t)tok * IN_F;
    float acc[NEXP];
    #pragma unroll
    for (int e = 0; e < NEXP; e++) acc[e] = 0.f;

    for (int k = lane * 4; k < IN_F; k += 128) {
        float4 xv = *(const float4*)(xr + k);
        #pragma unroll
        for (int e = 0; e < NEXP; e++) {
            float4 wv = *(const float4*)(Wr + (size_t)e * IN_F + k);
            acc[e] += xv.x * wv.x + xv.y * wv.y + xv.z * wv.z + xv.w * wv.w;
        }
    }
    #pragma unroll
    for (int e = 0; e < NEXP; e++)
        #pragma unroll
        for (int off = 16; off > 0; off >>= 1)
            acc[e] += __shfl_xor_sync(0xFFFFFFFFu, acc[e], off);

    int i0 = 0; float v0 = acc[0];
    #pragma unroll
    for (int e = 1; e < NEXP; e++) if (acc[e] > v0) { v0 = acc[e]; i0 = e; }
    int i1 = -1; float v1 = -3.4e38f;
    #pragma unroll
    for (int e = 0; e < NEXP; e++) if (e != i0 && acc[e] > v1) { v1 = acc[e]; i1 = e; }

    const float ex = expf(v1 - v0);
    const float w0 = 1.f / (1.f + ex);
    const float w1 = ex / (1.f + ex);

    #pragma unroll
    for (int j = 0; j < 4; j++) {
        int c = lane + j * 32;
        int e = c >> 4;
        float f = (e == i0) ? w0 : (e == i1) ? w1 : 0.f;
        float sum = 0.f;
        #pragma unroll
        for (int p = 0; p < KSPLIT; p++)
            sum += g_si[(size_t)p * BT * ERC + (size_t)tok * ERC + c];
        g_sih[(size_t)tok * ERC + c] = __float2half_rn(sum * f);
    }
}

// ---------------------------------------------------------------------------
extern "C" void kernel_launch(void* const* d_in, const int* in_sizes, int n_in,
                              void* d_out, int out_size)
{
    const float* x  = (const float*)d_in[0];   // [B,T,IN]
    const float* Wb = (const float*)d_in[1];   // [OUT,IN]
    const float* bb = (const float*)d_in[2];   // [OUT]
    const float* Wr = (const float*)d_in[3];   // [E,IN]
    const float* Aw = (const float*)d_in[4];   // [E,R,IN] == A_all [ERC][IN]
    const float* Bw = (const float*)d_in[5];   // [E,OUT,R]
    float* out = (float*)d_out;

    __half *xh, *wbh, *awh, *sih, *ballh;
    float* si;
    cudaGetSymbolAddress((void**)&xh,    g_xh);
    cudaGetSymbolAddress((void**)&wbh,   g_wbh);
    cudaGetSymbolAddress((void**)&awh,   g_awh);
    cudaGetSymbolAddress((void**)&si,    g_si);
    cudaGetSymbolAddress((void**)&sih,   g_sih);
    cudaGetSymbolAddress((void**)&ballh, g_ballh);

    cudaFuncSetAttribute(gemm_f16_kernel,
                         cudaFuncAttributeMaxDynamicSharedMemorySize, SMEM_BYTES);

    // 0) fp32 -> fp16 conversions (round-to-nearest)
    f2h_kernel<<<(size_t)BT * IN_F / 2048, 256>>>(x, xh);
    f2h_kernel<<<(size_t)OUT_F * IN_F / 2048, 256>>>(Wb, wbh);
    f2h_kernel<<<(size_t)ERC * IN_F / 2048, 256>>>(Aw, awh);
    prep_ball_kernel<<<(OUT_F * ERC) / 256, 256>>>(Bw);

    // 1) si partials = x @ A_all^T   (M=8192, N=128, K=4096, split-K x4)
    dim3 g1(ERC / BN, BT / BM, KSPLIT);
    gemm_f16_kernel<<<g1, 256, SMEM_BYTES>>>(
        xh, IN_F, awh, IN_F, IN_F / KSPLIT,
        nullptr, 0, nullptr, 0, 0,
        si, ERC, nullptr, (size_t)BT * ERC);

    // 2) router + top-2 softmax + split-K reduce + scale -> fp16 si
    router_mask_kernel<<<BT / 8, 256>>>(x, Wr);

    // 3) out = x @ W_base^T (K=4096) + si @ B_all^T (K=128) + b
    dim3 g2(OUT_F / BN, BT / BM, 1);
    gemm_f16_kernel<<<g2, 256, SMEM_BYTES>>>(
        xh, IN_F, wbh, IN_F, IN_F,
        sih, ERC, ballh, ERC, ERC,
        out, OUT_F, bb, 0);
}